// round 13
// baseline (speedup 1.0000x reference)
#include <cuda_runtime.h>

// Problem constants (fixed by the reference)
#define BATCH 16
#define MCTRL 64          // control points per dim
#define DEG   3           // degree P == Q
#define KLEN  68          // MCTRL + DEG + 1 knots
#define NSPAN 62          // KLEN - 2*DEG candidate spans
#define TPTS  256         // OUT_U == OUT_V
#define IPB   8           // output rows (i values) per block
#define THREADS 512       // two 256-thread halves; each half owns 4 rows

// ---------------------------------------------------------------------------
// Per-thread basis: binary-search span + Cox-de Boor (deg 3), the reference's
// arithmetic (fast division; error ~1e-7 vs 1e-3 tolerance).
// Span = argmin over cand[s] = (tp-U[3+s] > 1e-8) ? tp-U[3+s] : 1.
// U[3..64] strictly increasing -> d strictly decreasing -> minimum is the
// LAST s with d > 1e-8 -> 6-step binary search. s=0 always valid.
// ---------------------------------------------------------------------------
__device__ __forceinline__ void basis_at(const float* __restrict__ U,
                                         float tp, float N[DEG + 1], int& span)
{
    int lo = 0, hi = NSPAN - 1;
    #pragma unroll
    for (int it = 0; it < 6; it++) {           // ceil(log2(62)) = 6
        const int mid = (lo + hi + 1) >> 1;
        if (lo < hi) {
            if (tp - U[DEG + mid] > 1e-8f) lo = mid; else hi = mid - 1;
        }
    }
    span = lo + DEG;

    N[0] = 1.0f;
    #pragma unroll
    for (int k = 1; k <= DEG; k++) {
        float saved = 0.0f;
        #pragma unroll
        for (int r = 0; r < k; r++) {
            const float K1 = U[span + r + 1];
            const float K2 = U[span + 1 - k + r];
            const float temp = __fdividef(N[r], (K1 - tp) + (tp - K2));
            N[r] = saved + (K1 - tp) * temp;
            saved = (tp - K2) * temp;
        }
        N[k] = saved;
    }
}

// 32-lane inclusive scan via shfl
__device__ __forceinline__ float warp_iscan(float v, int lane) {
    #pragma unroll
    for (int off = 1; off < 32; off <<= 1) {
        const float t = __shfl_up_sync(0xffffffffu, v, off);
        if (lane >= off) v += t;
    }
    return v;
}

// ---------------------------------------------------------------------------
// Fused kernel. Block = (i-tile of IPB=8 rows, batch b), 512 threads.
// Thread tid works on eval point j = tid & 255; half = tid >> 8 owns rows
// half*4 .. half*4+3 of the tile. 512-thread blocks keep IPB=8's low
// issue-per-output while restoring full warp occupancy (4 CTAs/SM).
//   0) warp-0 shuffle scan of the 68 knots -> normalized U in smem
//      (Nv==Nu: the reference builds V from knot_u too, and u==v).
//   1) EVERY thread computes the basis for its j in registers (redundant
//      across halves -> latency-hiding ALU, zero smem reads later).
//      Lower-half threads with j==i0+k publish theirs as row bases (u==v).
//   2) row blend straight from global (coalesced LDG.32, L2-resident ctrl),
//      4 rows per thread.
//   3) column stencil (4 LDS.128/output) + direct stores, 4 rows per thread.
// ---------------------------------------------------------------------------
__global__ void __launch_bounds__(THREADS) fused_kernel(
    const float4* __restrict__ ctrl,     // [B][64][64] float4
    const float*  __restrict__ knot_u,   // [B][68]
    float*        __restrict__ out)      // [B][256][256][3]
{
    const int b    = blockIdx.y;
    const int i0   = blockIdx.x * IPB;
    const int tid  = threadIdx.x;
    const int j    = tid & (TPTS - 1);
    const int half = tid >> 8;           // 0 or 1

    __shared__ float  U[KLEN];
    __shared__ float4 blend[IPB][MCTRL];      // 8 KB
    __shared__ float  wu_s [IPB][4];
    __shared__ int    row0_s[IPB];

    // --- Stage 0: warp-0 scan of knots + normalize ---
    if (tid < 32) {
        const float* kb = knot_u + b * KLEN;
        float a0 = kb[tid];
        float a1 = kb[tid + 32];
        float a2 = (tid < KLEN - 64) ? kb[tid + 64] : 0.0f;
        const float k0 = __shfl_sync(0xffffffffu, a0, 0);  // knot[0]

        a0 = warp_iscan(a0, tid);
        const float tot0 = __shfl_sync(0xffffffffu, a0, 31);
        a1 = warp_iscan(a1, tid) + tot0;
        const float tot1 = __shfl_sync(0xffffffffu, a1, 31);
        a2 = warp_iscan(a2, tid) + tot1;

        const float last = __shfl_sync(0xffffffffu, a2, KLEN - 64 - 1); // c[67]
        const float inv  = 1.0f / (last - k0);
        U[tid]      = (a0 - k0) * inv;
        U[tid + 32] = (a1 - k0) * inv;
        if (tid < KLEN - 64) U[tid + 64] = (a2 - k0) * inv;
    }
    __syncthreads();

    // --- Stage 1: per-thread basis (registers); publish row bases ---
    float wv[DEG + 1];
    int   col0;
    {
        const float tp = 1e-5f + (float)j * ((1.0f - 2e-5f) / 255.0f);
        int span;
        basis_at(U, tp, wv, span);
        col0 = span - DEG;
        col0 = col0 < 0 ? 0 : (col0 > MCTRL - 4 ? MCTRL - 4 : col0);
    }
    if (tid < TPTS && (unsigned)(j - i0) < IPB) {   // lower half, j == i0+k
        const int k = j - i0;
        wu_s[k][0] = wv[0]; wu_s[k][1] = wv[1];
        wu_s[k][2] = wv[2]; wu_s[k][3] = wv[3];
        row0_s[k]  = col0;
    }
    __syncthreads();

    // --- Stage 2: row blends straight from global (4 rows per thread) ---
    // thread j <-> (col = j>>2, comp = j&3); float offset col*4+comp == j,
    // so each row read is a fully-coalesced 128B warp transaction (L2 hit).
    {
        const float* cbase = (const float*)ctrl + b * (MCTRL * MCTRL * 4);
        #pragma unroll
        for (int kk = 0; kk < IPB / 2; kk++) {
            const int k = half * (IPB / 2) + kk;
            const float* rp = cbase + row0_s[k] * (MCTRL * 4) + j;
            float acc;
            acc = wu_s[k][0] * rp[0];
            acc = fmaf(wu_s[k][1], rp[1 * MCTRL * 4], acc);
            acc = fmaf(wu_s[k][2], rp[2 * MCTRL * 4], acc);
            acc = fmaf(wu_s[k][3], rp[3 * MCTRL * 4], acc);
            ((float*)blend)[k * MCTRL * 4 + j] = acc;   // blend[k][col].comp
        }
    }
    __syncthreads();

    // --- Stage 3: column stencil + store (4 rows per thread) ---
    #pragma unroll
    for (int kk = 0; kk < IPB / 2; kk++) {
        const int k = half * (IPB / 2) + kk;
        const float4 c0 = blend[k][col0 + 0];
        const float4 c1 = blend[k][col0 + 1];
        const float4 c2 = blend[k][col0 + 2];
        const float4 c3 = blend[k][col0 + 3];
        const float x =
            fmaf(wv[0], c0.x, fmaf(wv[1], c1.x, fmaf(wv[2], c2.x, wv[3] * c3.x)));
        const float y =
            fmaf(wv[0], c0.y, fmaf(wv[1], c1.y, fmaf(wv[2], c2.y, wv[3] * c3.y)));
        const float z =
            fmaf(wv[0], c0.z, fmaf(wv[1], c1.z, fmaf(wv[2], c2.z, wv[3] * c3.z)));

        const int base = (b * TPTS + i0 + k) * (TPTS * 3) + j * 3;  // 32-bit
        out[base + 0] = x;
        out[base + 1] = y;
        out[base + 2] = z;
    }
}

// ---------------------------------------------------------------------------
// Launch: single fused kernel (knot_v is unused — the reference builds V
// from knot_u as well).
// ---------------------------------------------------------------------------
extern "C" void kernel_launch(void* const* d_in, const int* in_sizes, int n_in,
                              void* d_out, int out_size) {
    const float* ctrl   = (const float*)d_in[0];   // [16,64,64,4] f32
    const float* knot_u = (const float*)d_in[1];   // [16,68] f32
    (void)in_sizes; (void)n_in; (void)out_size;

    fused_kernel<<<dim3(TPTS / IPB, BATCH), THREADS>>>(
        (const float4*)ctrl, knot_u, (float*)d_out);
}

// round 15
// speedup vs baseline: 1.1866x; 1.1866x over previous
#include <cuda_runtime.h>

// Problem constants (fixed by the reference)
#define BATCH 16
#define MCTRL 64          // control points per dim
#define DEG   3           // degree P == Q
#define KLEN  68          // MCTRL + DEG + 1 knots
#define NSPAN 62          // KLEN - 2*DEG candidate spans
#define TPTS  256         // OUT_U == OUT_V
#define IPB   4           // output rows (i values) per block

// ---------------------------------------------------------------------------
// Per-thread basis: binary-search span + Cox-de Boor (deg 3), the reference's
// arithmetic (fast division; error ~1e-7 vs 1e-3 tolerance).
// Span = argmin over cand[s] = (tp-U[3+s] > 1e-8) ? tp-U[3+s] : 1.
// U[3..64] strictly increasing -> d strictly decreasing -> minimum is the
// LAST s with d > 1e-8 -> 6-step binary search. s=0 always valid.
// ---------------------------------------------------------------------------
__device__ __forceinline__ void basis_at(const float* __restrict__ U,
                                         float tp, float N[DEG + 1], int& span)
{
    int lo = 0, hi = NSPAN - 1;
    #pragma unroll
    for (int it = 0; it < 6; it++) {           // ceil(log2(62)) = 6
        const int mid = (lo + hi + 1) >> 1;
        if (lo < hi) {
            if (tp - U[DEG + mid] > 1e-8f) lo = mid; else hi = mid - 1;
        }
    }
    span = lo + DEG;

    N[0] = 1.0f;
    #pragma unroll
    for (int k = 1; k <= DEG; k++) {
        float saved = 0.0f;
        #pragma unroll
        for (int r = 0; r < k; r++) {
            const float K1 = U[span + r + 1];
            const float K2 = U[span + 1 - k + r];
            const float temp = __fdividef(N[r], (K1 - tp) + (tp - K2));
            N[r] = saved + (K1 - tp) * temp;
            saved = (tp - K2) * temp;
        }
        N[k] = saved;
    }
}

// 32-lane inclusive scan via shfl
__device__ __forceinline__ float warp_iscan(float v, int lane) {
    #pragma unroll
    for (int off = 1; off < 32; off <<= 1) {
        const float t = __shfl_up_sync(0xffffffffu, v, off);
        if (lane >= off) v += t;
    }
    return v;
}

// ---------------------------------------------------------------------------
// Fused kernel (validated best shape). Block = (i-tile of IPB=4 rows,
// batch b), 256 threads (one per j).
//   0) warp-0 shuffle scan of the 68 knots -> normalized U in smem
//      (Nv==Nu: the reference builds V from knot_u too, and u==v).
//   1) every thread: column basis in registers; threads with j==i0+k
//      PUBLISH theirs as row bases (row basis == column basis, u==v).
//   2) row blend straight from global (coalesced LDG.32, L2-resident ctrl):
//      thread (col,comp): blend[k][col].comp = sum_l wu[l]*ctrl[row0+l][col].comp
//   3) per j, per k: out = sum_r wv[r]*blend[k][col0+r]  (4 LDS.128/output),
//      direct STG.32 stores, 32-bit indexing.
// ---------------------------------------------------------------------------
__global__ void __launch_bounds__(TPTS) fused_kernel(
    const float4* __restrict__ ctrl,     // [B][64][64] float4
    const float*  __restrict__ knot_u,   // [B][68]
    float*        __restrict__ out)      // [B][256][256][3]
{
    const int b  = blockIdx.y;
    const int i0 = blockIdx.x * IPB;
    const int j  = threadIdx.x;

    __shared__ float  U[KLEN];
    __shared__ float4 blend[IPB][MCTRL];      // 4 KB
    __shared__ float  wu_s [IPB][4];
    __shared__ int    row0_s[IPB];

    // --- Stage 0: warp-0 scan of knots + normalize ---
    if (j < 32) {
        const float* kb = knot_u + b * KLEN;
        float a0 = kb[j];
        float a1 = kb[j + 32];
        float a2 = (j < KLEN - 64) ? kb[j + 64] : 0.0f;
        const float k0 = __shfl_sync(0xffffffffu, a0, 0);  // knot[0]

        a0 = warp_iscan(a0, j);
        const float tot0 = __shfl_sync(0xffffffffu, a0, 31);
        a1 = warp_iscan(a1, j) + tot0;
        const float tot1 = __shfl_sync(0xffffffffu, a1, 31);
        a2 = warp_iscan(a2, j) + tot1;

        const float last = __shfl_sync(0xffffffffu, a2, KLEN - 64 - 1); // c[67]
        const float inv  = 1.0f / (last - k0);
        U[j]      = (a0 - k0) * inv;
        U[j + 32] = (a1 - k0) * inv;
        if (j < KLEN - 64) U[j + 64] = (a2 - k0) * inv;
    }
    __syncthreads();

    // --- Stage 1: per-thread column basis (registers); publish row bases ---
    float wv[DEG + 1];
    int   col0;
    {
        const float tp = 1e-5f + (float)j * ((1.0f - 2e-5f) / 255.0f);
        int span;
        basis_at(U, tp, wv, span);
        col0 = span - DEG;
        col0 = col0 < 0 ? 0 : (col0 > MCTRL - 4 ? MCTRL - 4 : col0);
    }
    if ((unsigned)(j - i0) < IPB) {            // thread j == i0+k
        const int k = j - i0;
        wu_s[k][0] = wv[0]; wu_s[k][1] = wv[1];
        wu_s[k][2] = wv[2]; wu_s[k][3] = wv[3];
        row0_s[k]  = col0;
    }
    __syncthreads();

    // --- Stage 2: row blends straight from global ---
    // thread j <-> (col = j>>2, comp = j&3); float offset col*4+comp == j,
    // so each row read is a fully-coalesced 128B warp transaction (L2 hit).
    {
        const float* cbase = (const float*)ctrl + b * (MCTRL * MCTRL * 4);
        #pragma unroll
        for (int k = 0; k < IPB; k++) {
            const float* rp = cbase + row0_s[k] * (MCTRL * 4) + j;
            float acc;
            acc = wu_s[k][0] * rp[0];
            acc = fmaf(wu_s[k][1], rp[1 * MCTRL * 4], acc);
            acc = fmaf(wu_s[k][2], rp[2 * MCTRL * 4], acc);
            acc = fmaf(wu_s[k][3], rp[3 * MCTRL * 4], acc);
            ((float*)blend)[k * MCTRL * 4 + j] = acc;   // blend[k][col].comp
        }
    }
    __syncthreads();

    // --- Stage 3: column stencil + store (4 LDS.128 per output) ---
    #pragma unroll
    for (int k = 0; k < IPB; k++) {
        const float4 c0 = blend[k][col0 + 0];
        const float4 c1 = blend[k][col0 + 1];
        const float4 c2 = blend[k][col0 + 2];
        const float4 c3 = blend[k][col0 + 3];
        const float x =
            fmaf(wv[0], c0.x, fmaf(wv[1], c1.x, fmaf(wv[2], c2.x, wv[3] * c3.x)));
        const float y =
            fmaf(wv[0], c0.y, fmaf(wv[1], c1.y, fmaf(wv[2], c2.y, wv[3] * c3.y)));
        const float z =
            fmaf(wv[0], c0.z, fmaf(wv[1], c1.z, fmaf(wv[2], c2.z, wv[3] * c3.z)));

        const int base = (b * TPTS + i0 + k) * (TPTS * 3) + j * 3;  // 32-bit
        out[base + 0] = x;
        out[base + 1] = y;
        out[base + 2] = z;
    }
}

// ---------------------------------------------------------------------------
// Launch: single fused kernel (knot_v is unused — the reference builds V
// from knot_u as well).
// ---------------------------------------------------------------------------
extern "C" void kernel_launch(void* const* d_in, const int* in_sizes, int n_in,
                              void* d_out, int out_size) {
    const float* ctrl   = (const float*)d_in[0];   // [16,64,64,4] f32
    const float* knot_u = (const float*)d_in[1];   // [16,68] f32
    (void)in_sizes; (void)n_in; (void)out_size;

    fused_kernel<<<dim3(TPTS / IPB, BATCH), TPTS>>>(
        (const float4*)ctrl, knot_u, (float*)d_out);
}